// round 13
// baseline (speedup 1.0000x reference)
#include <cuda_runtime.h>
#include <cuda_fp16.h>
#include <cstdint>

// ---------------------------------------------------------------------------
// SKConv2d via mma.sync (fp16 in / fp32 acc):
//   out = im2col(x) @ W_eff + 2*bias
// Kernel 1 (merged prologue, 4.2KB smem for BOTH block types):
//   blocks [0,144)     : build W transposed to [o][k] fp16 (chunked smem reuse)
//   blocks [144,12688) : convert+transpose x -> g_Xh[b][pixel][c] fp16
// Kernel 2: implicit GEMM, BM=128, BN=256, BK=64, 512 threads,
//           16 warps (4Mx4N), warp tile 32x64 via m16n8k16.
//           A and B via cp.async, 3-stage pipeline, 1 barrier per 64-k chunk.
// ---------------------------------------------------------------------------

#define HH    56
#define WWd   56
#define Cc    128
#define OO    256
#define KK    1152
#define PLANE 3136
#define NN    100352
#define Tt    6
#define Rr    8
#define RR2   72

#define BM    128
#define BN    256
#define BK    64
#define NCHUNK 18          // 1152/64 ; tap = kt>>1
#define NSTAGE 3

// per stage: A 16KB (128 rows x 128B), B 32KB (256 rows x 128B)
#define STAGE_BYTES 49152
#define A_ST(s)  ((s) * STAGE_BYTES)
#define B_ST(s)  ((s) * STAGE_BYTES + 16384)
#define SMEM_BYTES (NSTAGE * STAGE_BYTES)      // 147456

#define PRO_PRE_BLOCKS 144            // 36 x 4 W-precompute tiles
#define PRO_CVT_BLOCKS 12544          // 98 x 4 x 32 transpose tiles

// W transposed fp16: g_Wh[o*KK + tap*128 + c]
__device__ __align__(16) __half g_Wh[OO * KK];
// x transposed fp16: g_Xh[(b*PLANE + p)*128 + c]
__device__ __align__(16) __half g_Xh[NN * Cc];

// ---------------------------------------------------------------------------
__device__ __forceinline__ uint32_t smem_u32(const void* p) {
    uint32_t a;
    asm("{ .reg .u64 t; cvta.to.shared.u64 t, %1; cvt.u32.u64 %0, t; }" : "=r"(a) : "l"(p));
    return a;
}
__device__ __forceinline__ uint32_t swz(uint32_t off) {   // 128B-row SW128 swizzle
    return off ^ ((off >> 3) & 0x70);
}
#define LDSM_X4(r0, r1, r2, r3, addr) \
    asm volatile("ldmatrix.sync.aligned.m8n8.x4.shared.b16 {%0,%1,%2,%3}, [%4];" \
        : "=r"(r0), "=r"(r1), "=r"(r2), "=r"(r3) : "r"(addr))
#define MMA16816(d, a0, a1, a2, a3, b0, b1)                                   \
    asm volatile("mma.sync.aligned.m16n8k16.row.col.f32.f16.f16.f32 "         \
        "{%0,%1,%2,%3}, {%4,%5,%6,%7}, {%8,%9}, {%0,%1,%2,%3};"               \
        : "+f"((d)[0]), "+f"((d)[1]), "+f"((d)[2]), "+f"((d)[3])              \
        : "r"(a0), "r"(a1), "r"(a2), "r"(a3), "r"(b0), "r"(b1))
#define CP_ASYNC16(dst, src) \
    asm volatile("cp.async.cg.shared.global [%0], [%1], 16;" :: "r"(dst), "l"(src) : "memory")
#define CP_ASYNC16Z(dst, src, sz) \
    asm volatile("cp.async.cg.shared.global [%0], [%1], 16, %2;" :: "r"(dst), "l"(src), "r"(sz) : "memory")
#define CP_COMMIT() asm volatile("cp.async.commit_group;" ::: "memory")
#define CP_WAIT1()  asm volatile("cp.async.wait_group 1;" ::: "memory")
#define CP_WAIT0()  asm volatile("cp.async.wait_group 0;" ::: "memory")

// ---------------------------------------------------------------------------
// Kernel 1: merged prologue. Grid 12688, block 256, 4.2KB smem total.
// ---------------------------------------------------------------------------
__global__ void prologue(const float* __restrict__ x,
                         const float* __restrict__ S1s,
                         const float* __restrict__ U1s,
                         const float* __restrict__ U2s,
                         const float* __restrict__ S2s) {
    __shared__ float buf[1056];     // 4.2KB, shared by both block types
    const int tid = threadIdx.x;

    if (blockIdx.x < PRO_PRE_BLOCKS) {
        // ---------------- W_eff precompute (chunked through buf) ----------------
        const int d0 = (blockIdx.x % 36) * 32;
        const int o0 = (blockIdx.x / 36) * 64;
        const int dd = tid & 31;
        const int og = (tid >> 5) * 8;

        float acc[8];
#pragma unroll
        for (int j = 0; j < 8; j++) acc[j] = 0.f;

        for (int t = 0; t < Tt; t++) {
            // --- term1: S1 [32][8] at buf[0:256], U1 [8][64] at buf[256:768] ---
            __syncthreads();        // protect buf from previous use
            {   int row = tid >> 3, col = tid & 7;
                buf[row * 8 + col] = S1s[(t * KK + d0 + row) * Rr + col]; }
#pragma unroll
            for (int i = 0; i < 2; i++) {
                int idx = tid + i * 256; int r = idx >> 6, o = idx & 63;
                buf[256 + r * 64 + o] = U1s[(t * Rr + r) * OO + o0 + o]; }
            __syncthreads();
#pragma unroll
            for (int r = 0; r < Rr; r++) {
                float a = buf[dd * 8 + r];
#pragma unroll
                for (int j = 0; j < 8; j++) acc[j] += a * buf[256 + r * 64 + og + j];
            }
            // --- term2: 9 chunks of 8 r2-rows ---
            for (int cch = 0; cch < 9; cch++) {
                __syncthreads();
                {   int row = tid >> 5, col = tid & 31;   // U2c [8][32] -> buf[0:256]
                    buf[row * 32 + col] =
                        U2s[(t * RR2 + cch * 8 + row) * KK + d0 + col]; }
#pragma unroll
                for (int i = 0; i < 2; i++) {             // S2c [8][64] -> buf[256:768]
                    int idx = tid + i * 256; int r2 = idx >> 6, o = idx & 63;
                    buf[256 + r2 * 64 + o] =
                        S2s[(t * RR2 + cch * 8 + r2) * OO + o0 + o]; }
                __syncthreads();
#pragma unroll
                for (int r2 = 0; r2 < 8; r2++) {
                    float a = buf[r2 * 32 + dd];
#pragma unroll
                    for (int j = 0; j < 8; j++)
                        acc[j] += a * buf[256 + r2 * 64 + og + j];
                }
            }
        }

        const int d   = d0 + dd;
        const int c   = d / 9;
        const int tap = d - 9 * c;
        const int krow = tap * 128 + c;
#pragma unroll
        for (int j = 0; j < 8; j++)
            g_Wh[(o0 + og + j) * KK + krow] = __float2half_rn(acc[j] * (1.0f / 6.0f));
    } else {
        // ---------------- x convert + transpose (tile = buf as [32][33]) --------
        float (*tile)[33] = reinterpret_cast<float (*)[33]>(buf);
        const int bid = blockIdx.x - PRO_PRE_BLOCKS;
        const int b   = bid / 392;            // 392 = 98 * 4
        const int rem = bid - b * 392;
        const int p0  = (rem % 98) * 32;
        const int c0  = (rem / 98) * 32;
        const int tx  = tid & 31;
        const int ty  = tid >> 5;
        const float* xb = x + (size_t)b * Cc * PLANE;
#pragma unroll
        for (int i = 0; i < 4; i++)
            tile[ty + 8 * i][tx] = xb[(size_t)(c0 + ty + 8 * i) * PLANE + p0 + tx];
        __syncthreads();
#pragma unroll
        for (int i = 0; i < 4; i++)
            g_Xh[(size_t)(b * PLANE + p0 + ty + 8 * i) * Cc + c0 + tx] =
                __float2half_rn(tile[tx][ty + 8 * i]);
    }
}

// ---------------------------------------------------------------------------
// Kernel 2: mma.sync implicit GEMM conv. Grid 784, block 512, 144KB dyn smem.
// ---------------------------------------------------------------------------
__global__ __launch_bounds__(512, 1)
void conv_mma(const float* __restrict__ bias,
              float* __restrict__ out) {
    extern __shared__ __align__(16) char smem[];
    const uint32_t sb = smem_u32(smem);

    const int tid  = threadIdx.x;
    const int lane = tid & 31;
    const int wid  = tid >> 5;
    const int wm   = wid & 3;      // 4 warps in M (32 rows each)
    const int wn   = wid >> 2;     // 4 warps in N (64 cols each)
    const int bm0  = blockIdx.x * BM;

    // ---- A-copy geometry: row ar = tid>>2, segs 2*(tid&3)+{0,1} (32B) ----
    const int ar   = tid >> 2;
    const int asg0 = (tid & 3) * 2;
    const int am   = bm0 + ar;
    const int ab   = am / PLANE;
    const int arem = am - ab * PLANE;
    const int aoh  = arem / WWd;
    const int aow  = arem - aoh * WWd;

    const char* xrow[9];     // row-start src per tap
    uint32_t    xsz[9];      // 16 if valid else 0
#pragma unroll
    for (int tap = 0; tap < 9; tap++) {
        const int kh = tap / 3, kw = tap - 3 * kh;
        const int ih = aoh + kh - 1, iw = aow + kw - 1;
        const bool ok = ((unsigned)ih < HH) && ((unsigned)iw < WWd);
        const int  off = ok ? (ih * WWd + iw) : 0;
        xrow[tap] = reinterpret_cast<const char*>(
                        g_Xh + (size_t)(ab * PLANE + off) * Cc);
        xsz[tap]  = ok ? 16u : 0u;
    }
    const char* wb = reinterpret_cast<const char*>(g_Wh);

    auto issueChunk = [&](int kt, int s) {
        const int tap = kt >> 1;
        const int c0b = (kt & 1) * 128;          // chunk channel-offset in bytes
        // A: 1024 x 16B (this thread: 2, same row)
#pragma unroll
        for (int i = 0; i < 2; i++) {
            const int seg = asg0 + i;
            CP_ASYNC16Z(sb + A_ST(s) + swz(ar * 128 + seg * 16),
                        xrow[tap] + c0b + seg * 16, xsz[tap]);
        }
        // B: 2048 x 16B (this thread: 4)
        const int k0 = kt * BK;
#pragma unroll
        for (int i = 0; i < 4; i++) {
            int f = tid + i * 512;
            int n = f >> 3, seg = f & 7;
            CP_ASYNC16(sb + B_ST(s) + swz(n * 128 + seg * 16),
                       wb + (size_t)(n * KK + k0 + seg * 8) * 2);
        }
        CP_COMMIT();
    };

    float acc[2][8][4];
#pragma unroll
    for (int i = 0; i < 2; i++)
#pragma unroll
        for (int j = 0; j < 8; j++)
#pragma unroll
            for (int q = 0; q < 4; q++) acc[i][j][q] = 0.f;

    issueChunk(0, 0); issueChunk(1, 1);

    int s = 0;           // stage of chunk kt
    int sn = 2;          // stage to fill next
#pragma unroll 1
    for (int kt = 0; kt < NCHUNK; kt++) {
        CP_WAIT1();                // group kt complete (<=1 group pending)
        __syncthreads();           // chunk kt visible; stage sn's readers done
        if (kt + 2 < NCHUNK) issueChunk(kt + 2, sn);
        else                 CP_COMMIT();    // keep group count aligned

        const uint32_t aB = sb + A_ST(s);
        const uint32_t bB = sb + B_ST(s);
#pragma unroll
        for (int ks = 0; ks < 4; ks++) {
            const int k0 = ks * 16;
            uint32_t af[2][4], bf[8][2];
#pragma unroll
            for (int i = 0; i < 2; i++) {
                const int mr = wm * 32 + i * 16 + (lane & 15);
                const int kc = k0 + (lane >> 4) * 8;
                LDSM_X4(af[i][0], af[i][1], af[i][2], af[i][3],
                        aB + swz(mr * 128 + kc * 2));
            }
#pragma unroll
            for (int jj = 0; jj < 4; jj++) {
                const int nr = wn * 64 + jj * 16 + ((lane >> 4) & 1) * 8 + (lane & 7);
                const int kc = k0 + ((lane >> 3) & 1) * 8;
                LDSM_X4(bf[2 * jj][0], bf[2 * jj][1], bf[2 * jj + 1][0], bf[2 * jj + 1][1],
                        bB + swz(nr * 128 + kc * 2));
            }
#pragma unroll
            for (int i = 0; i < 2; i++)
#pragma unroll
                for (int j = 0; j < 8; j++)
                    MMA16816(acc[i][j], af[i][0], af[i][1], af[i][2], af[i][3],
                             bf[j][0], bf[j][1]);
        }
        // advance stages (mod 3)
        s  = (s  == NSTAGE - 1) ? 0 : s + 1;
        sn = (sn == NSTAGE - 1) ? 0 : sn + 1;
        // no trailing barrier: next top barrier orders stage reuse
    }
    CP_WAIT0();

    // ---- epilogue: thread lane holds rows (l>>2, l>>2+8), cols 2*(l&3)+{0,1} ----
#pragma unroll
    for (int i = 0; i < 2; i++) {
        const int mg0 = bm0 + wm * 32 + i * 16 + (lane >> 2);
        const int b0e = mg0 / PLANE;
        const int p0e = mg0 - b0e * PLANE;
        const int mg1 = mg0 + 8;
        const int b1e = mg1 / PLANE;
        const int p1e = mg1 - b1e * PLANE;
        float* o0 = out + (size_t)b0e * (OO * PLANE) + p0e;
        float* o1 = out + (size_t)b1e * (OO * PLANE) + p1e;
#pragma unroll
        for (int j = 0; j < 8; j++) {
            const int o = wn * 64 + j * 8 + (lane & 3) * 2;
            const float bv0 = 2.0f * __ldg(bias + o);
            const float bv1 = 2.0f * __ldg(bias + o + 1);
            o0[(size_t)o * PLANE]       = acc[i][j][0] + bv0;
            o0[(size_t)(o + 1) * PLANE] = acc[i][j][1] + bv1;
            o1[(size_t)o * PLANE]       = acc[i][j][2] + bv0;
            o1[(size_t)(o + 1) * PLANE] = acc[i][j][3] + bv1;
        }
    }
}

// ---------------------------------------------------------------------------
extern "C" void kernel_launch(void* const* d_in, const int* in_sizes, int n_in,
                              void* d_out, int out_size) {
    const float* x    = (const float*)d_in[0];
    const float* S1s  = (const float*)d_in[1];
    const float* U1s  = (const float*)d_in[2];
    const float* U2s  = (const float*)d_in[3];
    const float* S2s  = (const float*)d_in[4];
    const float* bias = (const float*)d_in[5];
    float* out = (float*)d_out;

    cudaFuncSetAttribute(conv_mma, cudaFuncAttributeMaxDynamicSharedMemorySize,
                         SMEM_BYTES);

    prologue<<<PRO_PRE_BLOCKS + PRO_CVT_BLOCKS, 256>>>(x, S1s, U1s, U2s, S2s);
    conv_mma<<<784, 512, SMEM_BYTES>>>(bias, out);
}

// round 14
// speedup vs baseline: 1.1171x; 1.1171x over previous
#include <cuda_runtime.h>
#include <cuda_fp16.h>
#include <cstdint>

// ---------------------------------------------------------------------------
// SKConv2d via mma.sync (fp16 in / fp32 acc):
//   out = im2col(x) @ W_eff + 2*bias
// Kernel 0: convert+transpose x -> g_Xh[b][pixel][c] fp16.
// Kernel 1: build W transposed to [o][k] fp16, k = tap*128 + c.
// Kernel 2: implicit GEMM, BM=64, BN=256, BK=64, 256 threads,
//           8 warps (2Mx4N), warp tile 32x64 via m16n8k16.
//           2-stage cp.async pipeline, 2 CTAs/SM for cross-CTA overlap.
// ---------------------------------------------------------------------------

#define HH    56
#define WWd   56
#define Cc    128
#define OO    256
#define KK    1152
#define PLANE 3136
#define NN    100352
#define Tt    6
#define Rr    8
#define RR2   72

#define BM    64
#define BN    256
#define BK    64
#define NCHUNK 18          // 1152/64 ; tap = kt>>1
#define NSTAGE 2

// per stage: A 8KB (64 rows x 128B), B 32KB (256 rows x 128B)
#define STAGE_BYTES 40960
#define A_ST(s)  ((s) * STAGE_BYTES)
#define B_ST(s)  ((s) * STAGE_BYTES + 8192)
#define SMEM_BYTES (NSTAGE * STAGE_BYTES)      // 81920 -> 2 CTAs/SM

// W transposed fp16: g_Wh[o*KK + tap*128 + c]
__device__ __align__(16) __half g_Wh[OO * KK];
// x transposed fp16: g_Xh[(b*PLANE + p)*128 + c]
__device__ __align__(16) __half g_Xh[NN * Cc];

// ---------------------------------------------------------------------------
__device__ __forceinline__ uint32_t smem_u32(const void* p) {
    uint32_t a;
    asm("{ .reg .u64 t; cvta.to.shared.u64 t, %1; cvt.u32.u64 %0, t; }" : "=r"(a) : "l"(p));
    return a;
}
__device__ __forceinline__ uint32_t swz(uint32_t off) {   // 128B-row SW128 swizzle
    return off ^ ((off >> 3) & 0x70);
}
#define LDSM_X4(r0, r1, r2, r3, addr) \
    asm volatile("ldmatrix.sync.aligned.m8n8.x4.shared.b16 {%0,%1,%2,%3}, [%4];" \
        : "=r"(r0), "=r"(r1), "=r"(r2), "=r"(r3) : "r"(addr))
#define MMA16816(d, a0, a1, a2, a3, b0, b1)                                   \
    asm volatile("mma.sync.aligned.m16n8k16.row.col.f32.f16.f16.f32 "         \
        "{%0,%1,%2,%3}, {%4,%5,%6,%7}, {%8,%9}, {%0,%1,%2,%3};"               \
        : "+f"((d)[0]), "+f"((d)[1]), "+f"((d)[2]), "+f"((d)[3])              \
        : "r"(a0), "r"(a1), "r"(a2), "r"(a3), "r"(b0), "r"(b1))
#define CP_ASYNC16(dst, src) \
    asm volatile("cp.async.cg.shared.global [%0], [%1], 16;" :: "r"(dst), "l"(src) : "memory")
#define CP_ASYNC16Z(dst, src, sz) \
    asm volatile("cp.async.cg.shared.global [%0], [%1], 16, %2;" :: "r"(dst), "l"(src), "r"(sz) : "memory")
#define CP_COMMIT() asm volatile("cp.async.commit_group;" ::: "memory")
#define CP_WAIT1()  asm volatile("cp.async.wait_group 1;" ::: "memory")
#define CP_WAIT0()  asm volatile("cp.async.wait_group 0;" ::: "memory")

// ---------------------------------------------------------------------------
// Kernel 0: x [32,128,3136] fp32 -> g_Xh [32,3136,128] fp16 (tiled transpose).
// Grid (98, 4, 32), block 256. 4.2KB smem -> high occupancy.
// ---------------------------------------------------------------------------
__global__ void cvt_x(const float* __restrict__ x) {
    __shared__ float tile[32][33];
    const int b  = blockIdx.z;
    const int p0 = blockIdx.x * 32;
    const int c0 = blockIdx.y * 32;
    const int tx = threadIdx.x & 31;
    const int ty = threadIdx.x >> 5;
    const float* xb = x + (size_t)b * Cc * PLANE;
#pragma unroll
    for (int i = 0; i < 4; i++)
        tile[ty + 8 * i][tx] = xb[(size_t)(c0 + ty + 8 * i) * PLANE + p0 + tx];
    __syncthreads();
#pragma unroll
    for (int i = 0; i < 4; i++)
        g_Xh[(size_t)(b * PLANE + p0 + ty + 8 * i) * Cc + c0 + tx] =
            __float2half_rn(tile[tx][ty + 8 * i]);
}

// ---------------------------------------------------------------------------
// Kernel 1: precompute W_eff -> g_Wh[o][tap*128+c] fp16.
// Grid (36, 4): 32-d x 64-o tiles. 256 threads.
// ---------------------------------------------------------------------------
__global__ void precompute_w(const float* __restrict__ S1s,
                             const float* __restrict__ U1s,
                             const float* __restrict__ U2s,
                             const float* __restrict__ S2s) {
    __shared__ float sS1[32][8];
    __shared__ float sU1[8][64];
    __shared__ float sU2[72][32];
    __shared__ float sS2[72][64];

    const int tid = threadIdx.x;
    const int d0 = blockIdx.x * 32;
    const int o0 = blockIdx.y * 64;
    const int dd = tid & 31;
    const int og = (tid >> 5) * 8;

    float acc[8];
#pragma unroll
    for (int j = 0; j < 8; j++) acc[j] = 0.f;

    for (int t = 0; t < Tt; t++) {
        {   int row = tid >> 3, col = tid & 7;
            sS1[row][col] = S1s[(t * KK + d0 + row) * Rr + col]; }
#pragma unroll
        for (int i = 0; i < 2; i++) {
            int idx = tid + i * 256; int r = idx >> 6, o = idx & 63;
            sU1[r][o] = U1s[(t * Rr + r) * OO + o0 + o]; }
#pragma unroll
        for (int i = 0; i < 9; i++) {
            int idx = tid + i * 256; int r2 = idx >> 5, d = idx & 31;
            sU2[r2][d] = U2s[(t * RR2 + r2) * KK + d0 + d]; }
#pragma unroll
        for (int i = 0; i < 18; i++) {
            int idx = tid + i * 256; int r2 = idx >> 6, o = idx & 63;
            sS2[r2][o] = S2s[(t * RR2 + r2) * OO + o0 + o]; }
        __syncthreads();

#pragma unroll
        for (int r = 0; r < Rr; r++) {
            float a = sS1[dd][r];
#pragma unroll
            for (int j = 0; j < 8; j++) acc[j] += a * sU1[r][og + j];
        }
        for (int r2 = 0; r2 < RR2; r2++) {
            float a = sU2[r2][dd];
#pragma unroll
            for (int j = 0; j < 8; j++) acc[j] += a * sS2[r2][og + j];
        }
        __syncthreads();
    }

    const int d   = d0 + dd;
    const int c   = d / 9;
    const int tap = d - 9 * c;
    const int krow = tap * 128 + c;
#pragma unroll
    for (int j = 0; j < 8; j++)
        g_Wh[(o0 + og + j) * KK + krow] = __float2half_rn(acc[j] * (1.0f / 6.0f));
}

// ---------------------------------------------------------------------------
// Kernel 2: mma.sync implicit GEMM conv. Grid 1568, block 256, 80KB dyn smem.
// ---------------------------------------------------------------------------
__global__ __launch_bounds__(256, 2)
void conv_mma(const float* __restrict__ bias,
              float* __restrict__ out) {
    extern __shared__ __align__(16) char smem[];
    const uint32_t sb = smem_u32(smem);

    const int tid  = threadIdx.x;
    const int lane = tid & 31;
    const int wid  = tid >> 5;
    const int wm   = wid & 1;      // 2 warps in M (32 rows each)
    const int wn   = wid >> 1;     // 4 warps in N (64 cols each)
    const int bm0  = blockIdx.x * BM;

    // ---- A-copy geometry: row ar = tid>>2 (0..63), segs 2*(tid&3)+{0,1} ----
    const int ar   = tid >> 2;
    const int asg0 = (tid & 3) * 2;
    const int am   = bm0 + ar;
    const int ab   = am / PLANE;
    const int arem = am - ab * PLANE;
    const int aoh  = arem / WWd;
    const int aow  = arem - aoh * WWd;

    const char* xrow[9];     // row-start src per tap
    uint32_t    xsz[9];      // 16 if valid else 0
#pragma unroll
    for (int tap = 0; tap < 9; tap++) {
        const int kh = tap / 3, kw = tap - 3 * kh;
        const int ih = aoh + kh - 1, iw = aow + kw - 1;
        const bool ok = ((unsigned)ih < HH) && ((unsigned)iw < WWd);
        const int  off = ok ? (ih * WWd + iw) : 0;
        xrow[tap] = reinterpret_cast<const char*>(
                        g_Xh + (size_t)(ab * PLANE + off) * Cc);
        xsz[tap]  = ok ? 16u : 0u;
    }
    const char* wb = reinterpret_cast<const char*>(g_Wh);

    auto issueChunk = [&](int kt, int s) {
        const int tap = kt >> 1;
        const int c0b = (kt & 1) * 128;          // chunk channel-offset in bytes
        // A: 512 x 16B (this thread: 2, same row)
#pragma unroll
        for (int i = 0; i < 2; i++) {
            const int seg = asg0 + i;
            CP_ASYNC16Z(sb + A_ST(s) + swz(ar * 128 + seg * 16),
                        xrow[tap] + c0b + seg * 16, xsz[tap]);
        }
        // B: 2048 x 16B (this thread: 8)
        const int k0 = kt * BK;
#pragma unroll
        for (int i = 0; i < 8; i++) {
            int f = tid + i * 256;
            int n = f >> 3, seg = f & 7;
            CP_ASYNC16(sb + B_ST(s) + swz(n * 128 + seg * 16),
                       wb + (size_t)(n * KK + k0 + seg * 8) * 2);
        }
        CP_COMMIT();
    };

    float acc[2][8][4];
#pragma unroll
    for (int i = 0; i < 2; i++)
#pragma unroll
        for (int j = 0; j < 8; j++)
#pragma unroll
            for (int q = 0; q < 4; q++) acc[i][j][q] = 0.f;

    issueChunk(0, 0); issueChunk(1, 1);

#pragma unroll 1
    for (int kt = 0; kt < NCHUNK; kt++) {
        CP_WAIT1();                // group kt complete (<=1 group pending)
        __syncthreads();           // chunk kt visible to all threads

        const int s = kt & 1;
        const uint32_t aB = sb + A_ST(s);
        const uint32_t bB = sb + B_ST(s);
#pragma unroll
        for (int ks = 0; ks < 4; ks++) {
            const int k0 = ks * 16;
            uint32_t af[2][4], bf[8][2];
#pragma unroll
            for (int i = 0; i < 2; i++) {
                const int mr = wm * 32 + i * 16 + (lane & 15);
                const int kc = k0 + (lane >> 4) * 8;
                LDSM_X4(af[i][0], af[i][1], af[i][2], af[i][3],
                        aB + swz(mr * 128 + kc * 2));
            }
#pragma unroll
            for (int jj = 0; jj < 4; jj++) {
                const int nr = wn * 64 + jj * 16 + ((lane >> 4) & 1) * 8 + (lane & 7);
                const int kc = k0 + ((lane >> 3) & 1) * 8;
                LDSM_X4(bf[2 * jj][0], bf[2 * jj][1], bf[2 * jj + 1][0], bf[2 * jj + 1][1],
                        bB + swz(nr * 128 + kc * 2));
            }
#pragma unroll
            for (int i = 0; i < 2; i++)
#pragma unroll
                for (int j = 0; j < 8; j++)
                    MMA16816(acc[i][j], af[i][0], af[i][1], af[i][2], af[i][3],
                             bf[j][0], bf[j][1]);
        }

        __syncthreads();           // all reads of stage s done before refill
        if (kt + 2 < NCHUNK) issueChunk(kt + 2, s);
        else                 CP_COMMIT();    // keep group count aligned
    }
    CP_WAIT0();

    // ---- epilogue: thread lane holds rows (l>>2, l>>2+8), cols 2*(l&3)+{0,1} ----
#pragma unroll
    for (int i = 0; i < 2; i++) {
        const int mg0 = bm0 + wm * 32 + i * 16 + (lane >> 2);
        const int b0e = mg0 / PLANE;
        const int p0e = mg0 - b0e * PLANE;
        const int mg1 = mg0 + 8;
        const int b1e = mg1 / PLANE;
        const int p1e = mg1 - b1e * PLANE;
        float* o0 = out + (size_t)b0e * (OO * PLANE) + p0e;
        float* o1 = out + (size_t)b1e * (OO * PLANE) + p1e;
#pragma unroll
        for (int j = 0; j < 8; j++) {
            const int o = wn * 64 + j * 8 + (lane & 3) * 2;
            const float bv0 = 2.0f * __ldg(bias + o);
            const float bv1 = 2.0f * __ldg(bias + o + 1);
            o0[(size_t)o * PLANE]       = acc[i][j][0] + bv0;
            o0[(size_t)(o + 1) * PLANE] = acc[i][j][1] + bv1;
            o1[(size_t)o * PLANE]       = acc[i][j][2] + bv0;
            o1[(size_t)(o + 1) * PLANE] = acc[i][j][3] + bv1;
        }
    }
}

// ---------------------------------------------------------------------------
extern "C" void kernel_launch(void* const* d_in, const int* in_sizes, int n_in,
                              void* d_out, int out_size) {
    const float* x    = (const float*)d_in[0];
    const float* S1s  = (const float*)d_in[1];
    const float* U1s  = (const float*)d_in[2];
    const float* U2s  = (const float*)d_in[3];
    const float* S2s  = (const float*)d_in[4];
    const float* bias = (const float*)d_in[5];
    float* out = (float*)d_out;

    cudaFuncSetAttribute(conv_mma, cudaFuncAttributeMaxDynamicSharedMemorySize,
                         SMEM_BYTES);

    cvt_x<<<dim3(98, 4, 32), 256>>>(x);
    precompute_w<<<dim3(36, 4), 256>>>(S1s, U1s, U2s, S2s);
    conv_mma<<<1568, 256, SMEM_BYTES>>>(bias, out);
}

// round 15
// speedup vs baseline: 1.1589x; 1.0374x over previous
#include <cuda_runtime.h>
#include <cuda_fp16.h>
#include <cstdint>

// ---------------------------------------------------------------------------
// SKConv2d via mma.sync (fp16 in / fp32 acc):
//   out = im2col(x) @ W_eff + 2*bias
// Kernel 0: convert+transpose x -> g_Xh[b][pixel][c] fp16 (128B-line stores).
// Kernel 1: build W transposed to [o][k] fp16, k = tap*128 + c.
// Kernel 2: implicit GEMM, BM=64, BN=256, BK=64, 256 threads,
//           8 warps (2Mx4N), warp tile 32x64 via m16n8k16.
//           2-stage cp.async pipeline, 2 CTAs/SM, B-fragment ks-pipelining.
// ---------------------------------------------------------------------------

#define HH    56
#define WWd   56
#define Cc    128
#define OO    256
#define KK    1152
#define PLANE 3136
#define NN    100352
#define Tt    6
#define Rr    8
#define RR2   72

#define BM    64
#define BN    256
#define BK    64
#define NCHUNK 18          // 1152/64 ; tap = kt>>1
#define NSTAGE 2

// per stage: A 8KB (64 rows x 128B), B 32KB (256 rows x 128B)
#define STAGE_BYTES 40960
#define A_ST(s)  ((s) * STAGE_BYTES)
#define B_ST(s)  ((s) * STAGE_BYTES + 8192)
#define SMEM_BYTES (NSTAGE * STAGE_BYTES)      // 81920 -> 2 CTAs/SM

// W transposed fp16: g_Wh[o*KK + tap*128 + c]
__device__ __align__(16) __half g_Wh[OO * KK];
// x transposed fp16: g_Xh[(b*PLANE + p)*128 + c]
__device__ __align__(16) __half g_Xh[NN * Cc];

// ---------------------------------------------------------------------------
__device__ __forceinline__ uint32_t smem_u32(const void* p) {
    uint32_t a;
    asm("{ .reg .u64 t; cvta.to.shared.u64 t, %1; cvt.u32.u64 %0, t; }" : "=r"(a) : "l"(p));
    return a;
}
__device__ __forceinline__ uint32_t swz(uint32_t off) {   // 128B-row SW128 swizzle
    return off ^ ((off >> 3) & 0x70);
}
// pack two fp32 -> half2 bits; f0 -> low half (lower address)
__device__ __forceinline__ uint32_t pack_h2(float f0, float f1) {
    uint32_t r;
    asm("cvt.rn.f16x2.f32 %0, %1, %2;" : "=r"(r) : "f"(f1), "f"(f0));
    return r;
}
#define LDSM_X4(r0, r1, r2, r3, addr) \
    asm volatile("ldmatrix.sync.aligned.m8n8.x4.shared.b16 {%0,%1,%2,%3}, [%4];" \
        : "=r"(r0), "=r"(r1), "=r"(r2), "=r"(r3) : "r"(addr))
#define MMA16816(d, a0, a1, a2, a3, b0, b1)                                   \
    asm volatile("mma.sync.aligned.m16n8k16.row.col.f32.f16.f16.f32 "         \
        "{%0,%1,%2,%3}, {%4,%5,%6,%7}, {%8,%9}, {%0,%1,%2,%3};"               \
        : "+f"((d)[0]), "+f"((d)[1]), "+f"((d)[2]), "+f"((d)[3])              \
        : "r"(a0), "r"(a1), "r"(a2), "r"(a3), "r"(b0), "r"(b1))
#define CP_ASYNC16(dst, src) \
    asm volatile("cp.async.cg.shared.global [%0], [%1], 16;" :: "r"(dst), "l"(src) : "memory")
#define CP_ASYNC16Z(dst, src, sz) \
    asm volatile("cp.async.cg.shared.global [%0], [%1], 16, %2;" :: "r"(dst), "l"(src), "r"(sz) : "memory")
#define CP_COMMIT() asm volatile("cp.async.commit_group;" ::: "memory")
#define CP_WAIT1()  asm volatile("cp.async.wait_group 1;" ::: "memory")
#define CP_WAIT0()  asm volatile("cp.async.wait_group 0;" ::: "memory")

// ---------------------------------------------------------------------------
// Kernel 0: x [32,128,3136] fp32 -> g_Xh [32,3136,128] fp16.
// Grid (98, 32), block 256. Tile: 32 px x 128 ch. Stores are full 128B lines.
// ---------------------------------------------------------------------------
__global__ void cvt_x(const float* __restrict__ x) {
    __shared__ uint32_t h2t[32][65];      // [px][half2-ch], padded: conflict-free
    const int b  = blockIdx.y;
    const int p0 = blockIdx.x * 32;
    const int t  = threadIdx.x;
    const int px = t & 31;
    const int ty = t >> 5;                // 0..7

    const float* xb = x + (size_t)b * Cc * PLANE + p0 + px;
#pragma unroll
    for (int i = 0; i < 8; i++) {
        const int ch2 = ty + 8 * i;       // half2 index 0..63
        const float f0 = xb[(size_t)(2 * ch2)     * PLANE];
        const float f1 = xb[(size_t)(2 * ch2 + 1) * PLANE];
        h2t[px][ch2] = pack_h2(f0, f1);
    }
    __syncthreads();

    uint32_t* dst = reinterpret_cast<uint32_t*>(g_Xh + (size_t)(b * PLANE + p0) * Cc);
    const int lane = t & 31, w = t >> 5;
#pragma unroll
    for (int i = 0; i < 4; i++) {
        const int p = w * 4 + i;
        dst[p * 64 + lane]      = h2t[p][lane];        // 128B line
        dst[p * 64 + 32 + lane] = h2t[p][lane + 32];   // 128B line
    }
}

// ---------------------------------------------------------------------------
// Kernel 1: precompute W_eff -> g_Wh[o][tap*128+c] fp16.
// Grid (36, 4): 32-d x 64-o tiles. 256 threads.
// ---------------------------------------------------------------------------
__global__ void precompute_w(const float* __restrict__ S1s,
                             const float* __restrict__ U1s,
                             const float* __restrict__ U2s,
                             const float* __restrict__ S2s) {
    __shared__ float sS1[32][8];
    __shared__ float sU1[8][64];
    __shared__ float sU2[72][32];
    __shared__ float sS2[72][64];

    const int tid = threadIdx.x;
    const int d0 = blockIdx.x * 32;
    const int o0 = blockIdx.y * 64;
    const int dd = tid & 31;
    const int og = (tid >> 5) * 8;

    float acc[8];
#pragma unroll
    for (int j = 0; j < 8; j++) acc[j] = 0.f;

    for (int t = 0; t < Tt; t++) {
        {   int row = tid >> 3, col = tid & 7;
            sS1[row][col] = S1s[(t * KK + d0 + row) * Rr + col]; }
#pragma unroll
        for (int i = 0; i < 2; i++) {
            int idx = tid + i * 256; int r = idx >> 6, o = idx & 63;
            sU1[r][o] = U1s[(t * Rr + r) * OO + o0 + o]; }
#pragma unroll
        for (int i = 0; i < 9; i++) {
            int idx = tid + i * 256; int r2 = idx >> 5, d = idx & 31;
            sU2[r2][d] = U2s[(t * RR2 + r2) * KK + d0 + d]; }
#pragma unroll
        for (int i = 0; i < 18; i++) {
            int idx = tid + i * 256; int r2 = idx >> 6, o = idx & 63;
            sS2[r2][o] = S2s[(t * RR2 + r2) * OO + o0 + o]; }
        __syncthreads();

#pragma unroll
        for (int r = 0; r < Rr; r++) {
            float a = sS1[dd][r];
#pragma unroll
            for (int j = 0; j < 8; j++) acc[j] += a * sU1[r][og + j];
        }
        for (int r2 = 0; r2 < RR2; r2++) {
            float a = sU2[r2][dd];
#pragma unroll
            for (int j = 0; j < 8; j++) acc[j] += a * sS2[r2][og + j];
        }
        __syncthreads();
    }

    const int d   = d0 + dd;
    const int c   = d / 9;
    const int tap = d - 9 * c;
    const int krow = tap * 128 + c;
#pragma unroll
    for (int j = 0; j < 8; j++)
        g_Wh[(o0 + og + j) * KK + krow] = __float2half_rn(acc[j] * (1.0f / 6.0f));
}

// ---------------------------------------------------------------------------
// Kernel 2: mma.sync implicit GEMM conv. Grid 1568, block 256, 80KB dyn smem.
// ---------------------------------------------------------------------------
__global__ __launch_bounds__(256, 2)
void conv_mma(const float* __restrict__ bias,
              float* __restrict__ out) {
    extern __shared__ __align__(16) char smem[];
    const uint32_t sb = smem_u32(smem);

    const int tid  = threadIdx.x;
    const int lane = tid & 31;
    const int wid  = tid >> 5;
    const int wm   = wid & 1;      // 2 warps in M (32 rows each)
    const int wn   = wid >> 1;     // 4 warps in N (64 cols each)
    const int bm0  = blockIdx.x * BM;

    // ---- A-copy geometry: row ar = tid>>2 (0..63), segs 2*(tid&3)+{0,1} ----
    const int ar   = tid >> 2;
    const int asg0 = (tid & 3) * 2;
    const int am   = bm0 + ar;
    const int ab   = am / PLANE;
    const int arem = am - ab * PLANE;
    const int aoh  = arem / WWd;
    const int aow  = arem - aoh * WWd;

    const char* xbase = reinterpret_cast<const char*>(g_Xh);
    int      xoff[9];        // byte offset of im2col row per tap (fits 32-bit)
    uint32_t xmask = 0;      // per-tap validity bit
#pragma unroll
    for (int tap = 0; tap < 9; tap++) {
        const int kh = tap / 3, kw = tap - 3 * kh;
        const int ih = aoh + kh - 1, iw = aow + kw - 1;
        const bool ok = ((unsigned)ih < HH) && ((unsigned)iw < WWd);
        const int off = ok ? (ih * WWd + iw) : 0;
        xoff[tap] = (ab * PLANE + off) * (Cc * 2);
        if (ok) xmask |= (1u << tap);
    }
    const char* wb = reinterpret_cast<const char*>(g_Wh);

    auto issueChunk = [&](int kt, int s) {
        const int tap = kt >> 1;
        const int c0b = (kt & 1) * 128;          // chunk channel-offset in bytes
        const uint32_t sz = ((xmask >> tap) & 1u) * 16u;
        const char* src = xbase + xoff[tap] + c0b;
        // A: 512 x 16B (this thread: 2, same row)
#pragma unroll
        for (int i = 0; i < 2; i++) {
            const int seg = asg0 + i;
            CP_ASYNC16Z(sb + A_ST(s) + swz(ar * 128 + seg * 16),
                        src + seg * 16, sz);
        }
        // B: 2048 x 16B (this thread: 8)
        const int k0 = kt * BK;
#pragma unroll
        for (int i = 0; i < 8; i++) {
            int f = tid + i * 256;
            int n = f >> 3, seg = f & 7;
            CP_ASYNC16(sb + B_ST(s) + swz(n * 128 + seg * 16),
                       wb + (size_t)(n * KK + k0 + seg * 8) * 2);
        }
        CP_COMMIT();
    };

    float acc[2][8][4];
#pragma unroll
    for (int i = 0; i < 2; i++)
#pragma unroll
        for (int j = 0; j < 8; j++)
#pragma unroll
            for (int q = 0; q < 4; q++) acc[i][j][q] = 0.f;

    issueChunk(0, 0); issueChunk(1, 1);

#pragma unroll 1
    for (int kt = 0; kt < NCHUNK; kt++) {
        CP_WAIT1();                // group kt complete (<=1 group pending)
        __syncthreads();           // chunk kt visible to all threads

        const int s = kt & 1;
        const uint32_t aB = sb + A_ST(s);
        const uint32_t bB = sb + B_ST(s);

        // B fragments double-buffered across ks: load ks+1 under ks's mmas.
        uint32_t bf[2][8][2];
#pragma unroll
        for (int jj = 0; jj < 4; jj++) {        // preload ks=0
            const int nr = wn * 64 + jj * 16 + ((lane >> 4) & 1) * 8 + (lane & 7);
            const int kc = ((lane >> 3) & 1) * 8;
            LDSM_X4(bf[0][2 * jj][0], bf[0][2 * jj][1],
                    bf[0][2 * jj + 1][0], bf[0][2 * jj + 1][1],
                    bB + swz(nr * 128 + kc * 2));
        }
#pragma unroll
        for (int ks = 0; ks < 4; ks++) {
            const int k0 = ks * 16;
            uint32_t af[2][4];
#pragma unroll
            for (int i = 0; i < 2; i++) {
                const int mr = wm * 32 + i * 16 + (lane & 15);
                const int kc = k0 + (lane >> 4) * 8;
                LDSM_X4(af[i][0], af[i][1], af[i][2], af[i][3],
                        aB + swz(mr * 128 + kc * 2));
            }
            if (ks < 3) {
                const int k0n = k0 + 16;
#pragma unroll
                for (int jj = 0; jj < 4; jj++) {
                    const int nr = wn * 64 + jj * 16 + ((lane >> 4) & 1) * 8 + (lane & 7);
                    const int kc = k0n + ((lane >> 3) & 1) * 8;
                    LDSM_X4(bf[(ks + 1) & 1][2 * jj][0], bf[(ks + 1) & 1][2 * jj][1],
                            bf[(ks + 1) & 1][2 * jj + 1][0], bf[(ks + 1) & 1][2 * jj + 1][1],
                            bB + swz(nr * 128 + kc * 2));
                }
            }
#pragma unroll
            for (int i = 0; i < 2; i++)
#pragma unroll
                for (int j = 0; j < 8; j++)
                    MMA16816(acc[i][j], af[i][0], af[i][1], af[i][2], af[i][3],
                             bf[ks & 1][j][0], bf[ks & 1][j][1]);
        }

        __syncthreads();           // all reads of stage s done before refill
        if (kt + 2 < NCHUNK) issueChunk(kt + 2, s);
        else                 CP_COMMIT();    // keep group count aligned
    }
    CP_WAIT0();

    // ---- epilogue: thread lane holds rows (l>>2, l>>2+8), cols 2*(l&3)+{0,1} ----
#pragma unroll
    for (int i = 0; i < 2; i++) {
        const int mg0 = bm0 + wm * 32 + i * 16 + (lane >> 2);
        const int b0e = mg0 / PLANE;
        const int p0e = mg0 - b0e * PLANE;
        const int mg1 = mg0 + 8;
        const int b1e = mg1 / PLANE;
        const int p1e = mg1 - b1e * PLANE;
        float* o0 = out + (size_t)b0e * (OO * PLANE) + p0e;
        float* o1 = out + (size_t)b1e * (OO * PLANE) + p1e;
#pragma unroll
        for (int j = 0; j < 8; j++) {
            const int o = wn * 64 + j * 8 + (lane & 3) * 2;
            const float bv0 = 2.0f * __ldg(bias + o);
            const float bv1 = 2.0f * __ldg(bias + o + 1);
            o0[(size_t)o * PLANE]       = acc[i][j][0] + bv0;
            o0[(size_t)(o + 1) * PLANE] = acc[i][j][1] + bv1;
            o1[(size_t)o * PLANE]       = acc[i][j][2] + bv0;
            o1[(size_t)(o + 1) * PLANE] = acc[i][j][3] + bv1;
        }
    }
}

// ---------------------------------------------------------------------------
extern "C" void kernel_launch(void* const* d_in, const int* in_sizes, int n_in,
                              void* d_out, int out_size) {
    const float* x    = (const float*)d_in[0];
    const float* S1s  = (const float*)d_in[1];
    const float* U1s  = (const float*)d_in[2];
    const float* U2s  = (const float*)d_in[3];
    const float* S2s  = (const float*)d_in[4];
    const float* bias = (const float*)d_in[5];
    float* out = (float*)d_out;

    cudaFuncSetAttribute(conv_mma, cudaFuncAttributeMaxDynamicSharedMemorySize,
                         SMEM_BYTES);

    cvt_x<<<dim3(98, 32), 256>>>(x);
    precompute_w<<<dim3(36, 4), 256>>>(S1s, U1s, U2s, S2s);
    conv_mma<<<1568, 256, SMEM_BYTES>>>(bias, out);
}